// round 5
// baseline (speedup 1.0000x reference)
#include <cuda_runtime.h>
#include <cuda_bf16.h>
#include <math.h>

// Problem constants
#define BB   32
#define HH   14
#define WW   14
#define CC   32
#define KK   64
#define KS   5
#define OH   10
#define OW   10
#define PP   100      // OH*OW
#define NPOS 196      // H*W
#define MM   800      // KS*KS*C
#define IMG  6272     // NPOS*CC floats per batch
#define SIGB 1229312  // NPOS*NPOS*CC floats per batch of Sigma_in
#define SIGR 6304     // NPOS*CC + CC (diag row stride in floats)

// Scratch (device globals)
__device__ float2 g_wp [25 * 16 * KK];     // [ij][c2][k] weight channel-pairs
__device__ float2 g_wp2[25 * 16 * KK];     // squared
__device__ float  g_dv[BB * PP * KK];      // diag_vals
__device__ float  g_G [BB * PP * PP];      // Gram matrices
__device__ float  g_S [BB * NPOS * NPOS];  // position-Gram S = X X^T (4.9 MB)

// ---------------- f32x2 packed helpers ----------------
typedef unsigned long long ull;

__device__ __forceinline__ ull f2fma(ull a, ull b, ull c) {
    ull d;
    asm("fma.rn.f32x2 %0, %1, %2, %3;" : "=l"(d) : "l"(a), "l"(b), "l"(c));
    return d;
}
__device__ __forceinline__ float f2sum(ull v) {
    float lo, hi;
    asm("mov.b64 {%0, %1}, %2;" : "=f"(lo), "=f"(hi) : "l"(v));
    return lo + hi;
}

// ---------------- Kernel 0: weight pair-transpose (tiny, wide) ----------------
// g_wp[(ij*16+c2)*64 + k] = {w[ij*32+2c2][k], w[ij*32+2c2+1][k]}
__global__ __launch_bounds__(256) void k_prep_w(const float* __restrict__ w_mu) {
    int idx = blockIdx.x * 256 + threadIdx.x;        // 51200 total
    float v = w_mu[idx];                             // coalesced read
    int m = idx >> 6, k = idx & 63;
    int ij = m >> 5, c = m & 31;
    int c2 = c >> 1, half = c & 1;
    int o = ((ij * 16 + c2) * KK + k) * 2 + half;    // contiguous in k -> coalesced
    ((float*)g_wp)[o]  = v;
    ((float*)g_wp2)[o] = v * v;
}

// ---------------- Kernel A: mu_out + diag_vals ----------------
// grid (10 output-rows, 32 b), 256 threads. Tile = one output row (10 p's), 5 image rows.
// k = tid&63, pg = tid>>6 owns p columns {pg, pg+4, pg+8}.
__global__ __launch_bounds__(256) void k_mu_diag(const float* __restrict__ mu_in,
                                                 const float* __restrict__ Sg,
                                                 const float* __restrict__ w_sigma,
                                                 float* __restrict__ out_mu) {
    __shared__ __align__(16) float s_mu[5 * 14 * 32];   // 2240
    __shared__ __align__(16) float s_ds[5 * 14 * 32];   // 2240
    __shared__ float s_S[5 * 14];                       // per-pos channel sums
    __shared__ float s_tr[10];

    int tid = threadIdx.x;
    int pt  = blockIdx.x;               // output row = first image row
    int b   = blockIdx.y;

    // --- fused load: mu tile + Sigma-diag gather + channel sums ---
    {
        const float4* msrc = reinterpret_cast<const float4*>(mu_in + b * IMG + pt * 448);
        const float*  sb   = Sg + b * SIGB;
        float4* mdst = reinterpret_cast<float4*>(s_mu);
        float4* ddst = reinterpret_cast<float4*>(s_ds);
        int c4 = tid & 7;
        #pragma unroll
        for (int it = 0; it < 3; it++) {
            int t = tid + it * 256;
            bool actv = (t < 560);
            int pos_l = t >> 3;                          // 0..69
            float4 sg = make_float4(0.f, 0.f, 0.f, 0.f);
            if (actv) {
                mdst[t] = msrc[t];
                int pos = pt * 14 + pos_l;
                sg = *reinterpret_cast<const float4*>(sb + pos * SIGR + c4 * 4);
                ddst[t] = sg;
            }
            float part = sg.x + sg.y + sg.z + sg.w;
            part += __shfl_down_sync(0xffffffffu, part, 4, 8);
            part += __shfl_down_sync(0xffffffffu, part, 2, 8);
            part += __shfl_down_sync(0xffffffffu, part, 1, 8);
            if (actv && c4 == 0) s_S[pos_l] = part;
        }
    }
    __syncthreads();

    // --- trace per patch (10 p's, local row 0) ---
    if (tid < 10) {
        float s = 0.f;
        #pragma unroll
        for (int i = 0; i < KS; i++)
            #pragma unroll
            for (int j = 0; j < KS; j++)
                s += s_S[i * 14 + tid + j];
        s_tr[tid] = s;
    }
    __syncthreads();

    int k  = tid & 63;
    int pg = tid >> 6;

    ull accM[3], accV[3];
    #pragma unroll
    for (int jj = 0; jj < 3; jj++) { accM[jj] = 0ull; accV[jj] = 0ull; }

    const ull* wp  = reinterpret_cast<const ull*>(g_wp);
    const ull* wp2 = reinterpret_cast<const ull*>(g_wp2);

    #pragma unroll 1
    for (int ij = 0; ij < 25; ij++) {
        int i = ij / 5, j = ij % 5;
        int posl[3];
        #pragma unroll
        for (int jj = 0; jj < 3; jj++)
            posl[jj] = (i * 14 + (pg + 4 * jj) + j) * 32;
        const ull* wr  = wp  + ij * 16 * 64 + k;
        const ull* wr2 = wp2 + ij * 16 * 64 + k;
        #pragma unroll
        for (int c4 = 0; c4 < 8; c4++) {
            ull wA = __ldg(wr  + (2 * c4) * 64);
            ull wB = __ldg(wr  + (2 * c4 + 1) * 64);
            ull sA = __ldg(wr2 + (2 * c4) * 64);
            ull sB = __ldg(wr2 + (2 * c4 + 1) * 64);
            #pragma unroll
            for (int jj = 0; jj < 3; jj++) {
                if (pg + 4 * jj < 10) {
                    ulonglong2 a = *reinterpret_cast<const ulonglong2*>(s_mu + posl[jj] + c4 * 4);
                    ulonglong2 d = *reinterpret_cast<const ulonglong2*>(s_ds + posl[jj] + c4 * 4);
                    accM[jj] = f2fma(a.x, wA, accM[jj]);
                    accM[jj] = f2fma(a.y, wB, accM[jj]);
                    accV[jj] = f2fma(d.x, sA, accV[jj]);
                    accV[jj] = f2fma(d.y, sB, accV[jj]);
                }
            }
        }
    }

    float spk = log1pf(expf(w_sigma[k]));
    #pragma unroll
    for (int jj = 0; jj < 3; jj++) {
        int pl = pg + 4 * jj;
        if (pl < 10) {
            int p = pt * 10 + pl;
            out_mu[(b * PP + p) * KK + k] = f2sum(accM[jj]);
            g_dv[(b * PP + p) * KK + k]  = f2sum(accV[jj]) + spk * s_tr[pl];
        }
    }
}

// ---------------- Kernel B1: S = X X^T (wide) ----------------
// grid (7 x-tiles of 28 rows, 32 b), 256 threads.
__global__ __launch_bounds__(256) void k_gram_s(const float* __restrict__ mu_in) {
    __shared__ __align__(16) float2 s_yc[16 * 200];   // [c2][pos], padded

    int tid = threadIdx.x;
    int b   = blockIdx.y;
    int x0  = blockIdx.x * 28;
    const float* mb = mu_in + b * IMG;

    for (int t = tid; t < 16 * NPOS; t += 256) {
        int c2 = t & 15, pos = t >> 4;
        s_yc[c2 * 200 + pos] = *reinterpret_cast<const float2*>(mb + pos * 32 + c2 * 2);
    }
    __syncthreads();

    int lane = tid & 31, w = tid >> 5;
    float* Sb = g_S + b * (NPOS * NPOS);

    #pragma unroll 1
    for (int r = 0; r < 4; r++) {
        int xl = w + 8 * r;
        if (xl >= 28) break;
        int x = x0 + xl;

        ull xc[16];
        #pragma unroll
        for (int c2 = 0; c2 < 16; c2++)
            xc[c2] = *reinterpret_cast<const ull*>(s_yc + c2 * 200 + x);   // broadcast

        #pragma unroll 1
        for (int m = 0; m < 4; m++) {
            int pr = lane + 32 * m;
            if (pr >= 98) break;
            int y0 = 2 * pr;
            ull acc0 = 0ull, acc1 = 0ull;
            #pragma unroll
            for (int c2 = 0; c2 < 16; c2++) {
                ulonglong2 v = *reinterpret_cast<const ulonglong2*>(s_yc + c2 * 200 + y0);
                acc0 = f2fma(xc[c2], v.x, acc0);
                acc1 = f2fma(xc[c2], v.y, acc1);
            }
            float2 rr;
            rr.x = f2sum(acc0);
            rr.y = f2sum(acc1);
            *reinterpret_cast<float2*>(Sb + x * NPOS + y0) = rr;
        }
    }
}

// ---------------- Kernel B2: G[p,q] = 25-shift diagonal sum of S ----------------
// grid (4 p-tiles, 32 b), 256 threads.
__global__ __launch_bounds__(256) void k_gram_g() {
    int tid = threadIdx.x;
    int pt  = blockIdx.x;
    int b   = blockIdx.y;
    const float* Sb = g_S + b * (NPOS * NPOS);
    float* Gb = g_G + b * (PP * PP);

    #pragma unroll 1
    for (int idx = tid; idx < 25 * PP; idx += 256) {
        int p_l = idx / PP, q = idx - p_l * PP;
        int p  = pt * 25 + p_l;
        int pr = p / 10, pc = p - pr * 10;
        int qr = q / 10, qc = q - qr * 10;
        const float* s = Sb + (pr * 14 + pc) * NPOS + (qr * 14 + qc);
        float acc = 0.f;
        #pragma unroll
        for (int i = 0; i < KS; i++)
            #pragma unroll
            for (int j = 0; j < KS; j++)
                acc += __ldg(s + (i * 14 + j) * (NPOS + 1));
        Gb[p * PP + q] = acc;
    }
}

// ---------------- Kernel C: expand Sigma_out (pure bandwidth) ----------------
__global__ __launch_bounds__(256) void k_expand(const float* __restrict__ w_sigma,
                                                float* __restrict__ out) {
    __shared__ float  s_g[PP];
    __shared__ float4 s_sp[16];
    __shared__ float4 s_dv[16];

    int tid = threadIdx.x;
    int p = blockIdx.x, b = blockIdx.y;
    int bp = b * PP + p;

    if (tid < PP) s_g[tid] = g_G[b * (PP * PP) + p * PP + tid];
    if (tid >= 128 && tid < 144) {
        int k4 = (tid - 128) * 4;
        float4 sp;
        sp.x = log1pf(expf(w_sigma[k4]));
        sp.y = log1pf(expf(w_sigma[k4 + 1]));
        sp.z = log1pf(expf(w_sigma[k4 + 2]));
        sp.w = log1pf(expf(w_sigma[k4 + 3]));
        s_sp[tid - 128] = sp;
    }
    if (tid >= 160 && tid < 176)
        s_dv[tid - 160] = *reinterpret_cast<const float4*>(g_dv + bp * KK + (tid - 160) * 4);
    __syncthreads();

    float* orow = out + BB * PP * KK + bp * (PP * KK);

    #pragma unroll
    for (int it = 0; it < 7; it++) {
        int v = tid + it * 256;
        if (v < PP * 16) {
            int q = v >> 4, kc = v & 15, k4 = kc * 4;
            float g = s_g[q];
            float4 sp = s_sp[kc];
            float4 r;
            r.x = sp.x * g; r.y = sp.y * g; r.z = sp.z * g; r.w = sp.w * g;
            if (q == p) {
                float4 dv = s_dv[kc];
                r.x += dv.x; r.y += dv.y; r.z += dv.z; r.w += dv.w;
            }
            r.x = isfinite(r.x) ? r.x : 0.f;
            r.y = isfinite(r.y) ? r.y : 0.f;
            r.z = isfinite(r.z) ? r.z : 0.f;
            r.w = isfinite(r.w) ? r.w : 0.f;
            if (q == k4)     r.x = fabsf(r.x);
            if (q == k4 + 1) r.y = fabsf(r.y);
            if (q == k4 + 2) r.z = fabsf(r.z);
            if (q == k4 + 3) r.w = fabsf(r.w);
            *reinterpret_cast<float4*>(orow + 4 * v) = r;
        }
    }
}

// ---------------- launch ----------------
extern "C" void kernel_launch(void* const* d_in, const int* in_sizes, int n_in,
                              void* d_out, int out_size) {
    const float* mu_in    = (const float*)d_in[0];
    const float* Sigma_in = (const float*)d_in[1];
    const float* w_mu     = (const float*)d_in[2];
    const float* w_sigma  = (const float*)d_in[3];
    float* out = (float*)d_out;

    static cudaStream_t s2 = nullptr;
    static cudaEvent_t  eFork = nullptr, eJoin = nullptr;
    if (s2 == nullptr) {
        cudaStreamCreateWithFlags(&s2, cudaStreamNonBlocking);
        cudaEventCreateWithFlags(&eFork, cudaEventDisableTiming);
        cudaEventCreateWithFlags(&eJoin, cudaEventDisableTiming);
    }

    // side stream: Gram chain (depends only on mu_in)
    cudaEventRecord(eFork, 0);
    cudaStreamWaitEvent(s2, eFork, 0);
    k_gram_s<<<dim3(7, BB), 256, 0, s2>>>(mu_in);
    k_gram_g<<<dim3(4, BB), 256, 0, s2>>>();
    cudaEventRecord(eJoin, s2);

    // main stream: mu path
    k_prep_w<<<200, 256>>>(w_mu);
    k_mu_diag<<<dim3(10, BB), 256>>>(mu_in, Sigma_in, w_sigma, out);

    cudaStreamWaitEvent(0, eJoin, 0);
    k_expand<<<dim3(PP, BB), 256>>>(w_sigma, out);
}

// round 8
// speedup vs baseline: 1.2400x; 1.2400x over previous
#include <cuda_runtime.h>
#include <cuda_bf16.h>
#include <math.h>

// Problem constants
#define BB   32
#define HH   14
#define WW   14
#define CC   32
#define KK   64
#define KS   5
#define OH   10
#define OW   10
#define PP   100      // OH*OW
#define NPOS 196      // H*W
#define MM   800      // KS*KS*C
#define IMG  6272     // NPOS*CC floats per batch
#define SIGB 1229312  // NPOS*NPOS*CC floats per batch of Sigma_in
#define SIGR 6304     // NPOS*CC + CC (diag row stride in floats)

// Scratch (device globals)
__device__ float g_dv[BB * PP * KK];       // diag_vals
__device__ float g_G [BB * PP * PP];       // Gram matrices
__device__ float g_S [BB * NPOS * NPOS];   // position-Gram S = X X^T (4.9 MB)

// ---------------- f32x2 packed helpers ----------------
typedef unsigned long long ull;

__device__ __forceinline__ ull f2fma(ull a, ull b, ull c) {
    ull d;
    asm("fma.rn.f32x2 %0, %1, %2, %3;" : "=l"(d) : "l"(a), "l"(b), "l"(c));
    return d;
}
__device__ __forceinline__ ull f2mul(ull a, ull b) {
    ull d;
    asm("mul.rn.f32x2 %0, %1, %2;" : "=l"(d) : "l"(a), "l"(b));
    return d;
}
__device__ __forceinline__ float f2sum(ull v) {
    float lo, hi;
    asm("mov.b64 {%0, %1}, %2;" : "=f"(lo), "=f"(hi) : "l"(v));
    return lo + hi;
}

// ---------------- Kernel A: mu_out + diag_vals ----------------
// grid (5 ptiles of 20 p, 32 b), 256 threads (8 warps).
// kk = tid&63 (one k per thread), pg = tid>>6 owns p_local = pg*5 + {0..4}.
// Weight stage (one 5x5 tap = 32ch x 64k = 8KB) staged in smem via
// register-prefetch + STS; transposed to channel-pair layout on store.
__global__ __launch_bounds__(256) void k_mu_diag(const float* __restrict__ mu_in,
                                                 const float* __restrict__ Sg,
                                                 const float* __restrict__ w_mu,
                                                 const float* __restrict__ w_sigma,
                                                 float* __restrict__ out_mu) {
    __shared__ __align__(16) float s_w [2048];   // stage: [c2(16)][k(64)] ull pairs
    __shared__ __align__(16) float s_mu[2688];   // 6 rows x 14 x 32
    __shared__ __align__(16) float s_ds[2688];
    __shared__ float s_S[84];                    // per-pos channel sums (6x14)
    __shared__ float s_tr[20];

    int tid = threadIdx.x;
    int pt  = blockIdx.x;           // 0..4, output rows 2pt..2pt+1
    int b   = blockIdx.y;
    int kk  = tid & 63;
    int pg  = tid >> 6;

    const float4* wsrc = reinterpret_cast<const float4*>(w_mu);

    // --- prefetch weight stage 0 into registers ---
    float4 pf0 = __ldg(wsrc + tid);
    float4 pf1 = __ldg(wsrc + tid + 256);

    // --- fused load: mu tile (6 image rows) + Sigma-diag gather + channel sums ---
    {
        const float4* msrc = reinterpret_cast<const float4*>(mu_in + b * IMG + pt * 28 * 32);
        const float*  sb   = Sg + b * SIGB;
        float4* mdst = reinterpret_cast<float4*>(s_mu);
        float4* ddst = reinterpret_cast<float4*>(s_ds);
        int c4 = tid & 7;
        #pragma unroll
        for (int it = 0; it < 3; it++) {
            int t = tid + it * 256;
            bool actv = (t < 672);
            int pos_l = t >> 3;                   // 0..83
            float4 sg = make_float4(0.f, 0.f, 0.f, 0.f);
            if (actv) {
                mdst[t] = msrc[t];
                int pos = pt * 28 + pos_l;
                sg = *reinterpret_cast<const float4*>(sb + pos * SIGR + c4 * 4);
                ddst[t] = sg;
            }
            float part = sg.x + sg.y + sg.z + sg.w;
            part += __shfl_down_sync(0xffffffffu, part, 4, 8);
            part += __shfl_down_sync(0xffffffffu, part, 2, 8);
            part += __shfl_down_sync(0xffffffffu, part, 1, 8);
            if (actv && c4 == 0) s_S[pos_l] = part;
        }
    }
    __syncthreads();

    // --- trace per patch (20 p's) ---
    if (tid < 20) {
        int pr = tid / 10, pc = tid % 10;
        float s = 0.f;
        #pragma unroll
        for (int i = 0; i < KS; i++)
            #pragma unroll
            for (int j = 0; j < KS; j++)
                s += s_S[(pr + i) * 14 + pc + j];
        s_tr[tid] = s;
    }

    // p bases (local row pr in {0,1})
    int pbase[5];
    #pragma unroll
    for (int jp = 0; jp < 5; jp++) {
        int pl = pg * 5 + jp;                    // 0..19
        int pr = pl / 10, pc = pl % 10;
        pbase[jp] = (pr * 14 + pc) * 32;
    }

    ull accM[5], accV[5];
    #pragma unroll
    for (int jp = 0; jp < 5; jp++) { accM[jp] = 0ull; accV[jp] = 0ull; }

    // --- main loop over 25 kernel taps ---
    #pragma unroll 1
    for (int ij = 0; ij < 25; ij++) {
        __syncthreads();                 // previous tap's reads of s_w complete

        // store prefetched stage ij with channel-pair transpose:
        // float4 f covers channel c = f>>4, k = (f&15)*4 .. +3
        // dest float addr: (c>>1)*128 + k*2 + (c&1)
        {
            int f0 = tid;
            int c = f0 >> 4, kq = f0 & 15;
            float* bp = s_w + (c >> 1) * 128 + (c & 1) + kq * 8;
            bp[0] = pf0.x; bp[2] = pf0.y; bp[4] = pf0.z; bp[6] = pf0.w;
            int f1 = tid + 256;
            c = f1 >> 4; kq = f1 & 15;
            bp = s_w + (c >> 1) * 128 + (c & 1) + kq * 8;
            bp[0] = pf1.x; bp[2] = pf1.y; bp[4] = pf1.z; bp[6] = pf1.w;
        }
        // prefetch next stage (overlaps this tap's compute)
        if (ij + 1 < 25) {
            const float4* ws = wsrc + (ij + 1) * 512;
            pf0 = __ldg(ws + tid);
            pf1 = __ldg(ws + tid + 256);
        }
        __syncthreads();                 // stage ij visible

        int i = ij / 5, j = ij % 5;
        int sh = (i * 14 + j) * 32;

        #pragma unroll
        for (int c4 = 0; c4 < 8; c4++) {
            ull wA = *reinterpret_cast<const ull*>(s_w + (2 * c4) * 128 + kk * 2);
            ull wB = *reinterpret_cast<const ull*>(s_w + (2 * c4 + 1) * 128 + kk * 2);
            ull sA = f2mul(wA, wA);
            ull sB = f2mul(wB, wB);
            #pragma unroll
            for (int jp = 0; jp < 5; jp++) {
                int off = pbase[jp] + sh + c4 * 4;
                ulonglong2 a = *reinterpret_cast<const ulonglong2*>(s_mu + off);
                ulonglong2 d = *reinterpret_cast<const ulonglong2*>(s_ds + off);
                accM[jp] = f2fma(a.x, wA, accM[jp]);
                accM[jp] = f2fma(a.y, wB, accM[jp]);
                accV[jp] = f2fma(d.x, sA, accV[jp]);
                accV[jp] = f2fma(d.y, sB, accV[jp]);
            }
        }
    }

    float spk = log1pf(expf(w_sigma[kk]));
    #pragma unroll
    for (int jp = 0; jp < 5; jp++) {
        int pl = pg * 5 + jp;
        int p  = pt * 20 + pl;
        int base = (b * PP + p) * KK;
        out_mu[base + kk] = f2sum(accM[jp]);
        g_dv[base + kk]   = f2sum(accV[jp]) + spk * s_tr[pl];
    }
}

// ---------------- Kernel B1: S = X X^T (wide) ----------------
__global__ __launch_bounds__(256) void k_gram_s(const float* __restrict__ mu_in) {
    __shared__ __align__(16) float2 s_yc[16 * 200];   // [c2][pos], padded

    int tid = threadIdx.x;
    int b   = blockIdx.y;
    int x0  = blockIdx.x * 28;
    const float* mb = mu_in + b * IMG;

    for (int t = tid; t < 16 * NPOS; t += 256) {
        int c2 = t & 15, pos = t >> 4;
        s_yc[c2 * 200 + pos] = *reinterpret_cast<const float2*>(mb + pos * 32 + c2 * 2);
    }
    __syncthreads();

    int lane = tid & 31, wrp = tid >> 5;
    float* Sb = g_S + b * (NPOS * NPOS);

    #pragma unroll 1
    for (int r = 0; r < 4; r++) {
        int xl = wrp + 8 * r;
        if (xl >= 28) break;
        int x = x0 + xl;

        ull xc[16];
        #pragma unroll
        for (int c2 = 0; c2 < 16; c2++)
            xc[c2] = *reinterpret_cast<const ull*>(s_yc + c2 * 200 + x);   // broadcast

        #pragma unroll 1
        for (int m = 0; m < 4; m++) {
            int pr = lane + 32 * m;
            if (pr >= 98) break;
            int y0 = 2 * pr;
            ull acc0 = 0ull, acc1 = 0ull;
            #pragma unroll
            for (int c2 = 0; c2 < 16; c2++) {
                ulonglong2 v = *reinterpret_cast<const ulonglong2*>(s_yc + c2 * 200 + y0);
                acc0 = f2fma(xc[c2], v.x, acc0);
                acc1 = f2fma(xc[c2], v.y, acc1);
            }
            float2 rr;
            rr.x = f2sum(acc0);
            rr.y = f2sum(acc1);
            *reinterpret_cast<float2*>(Sb + x * NPOS + y0) = rr;
        }
    }
}

// ---------------- Kernel B2: G[p,q] = 25-shift diagonal sum of S ----------------
__global__ __launch_bounds__(256) void k_gram_g() {
    int tid = threadIdx.x;
    int pt  = blockIdx.x;
    int b   = blockIdx.y;
    const float* Sb = g_S + b * (NPOS * NPOS);
    float* Gb = g_G + b * (PP * PP);

    #pragma unroll 1
    for (int idx = tid; idx < 25 * PP; idx += 256) {
        int p_l = idx / PP, q = idx - p_l * PP;
        int p  = pt * 25 + p_l;
        int pr = p / 10, pc = p - pr * 10;
        int qr = q / 10, qc = q - qr * 10;
        const float* s = Sb + (pr * 14 + pc) * NPOS + (qr * 14 + qc);
        float acc = 0.f;
        #pragma unroll
        for (int i = 0; i < KS; i++)
            #pragma unroll
            for (int j = 0; j < KS; j++)
                acc += __ldg(s + (i * 14 + j) * (NPOS + 1));
        Gb[p * PP + q] = acc;
    }
}

// ---------------- Kernel C: expand Sigma_out (pure bandwidth) ----------------
__global__ __launch_bounds__(256) void k_expand(const float* __restrict__ w_sigma,
                                                float* __restrict__ out) {
    __shared__ float  s_g[PP];
    __shared__ float4 s_sp[16];
    __shared__ float4 s_dv[16];

    int tid = threadIdx.x;
    int p = blockIdx.x, b = blockIdx.y;
    int bp = b * PP + p;

    if (tid < PP) s_g[tid] = g_G[b * (PP * PP) + p * PP + tid];
    if (tid >= 128 && tid < 144) {
        int k4 = (tid - 128) * 4;
        float4 sp;
        sp.x = log1pf(expf(w_sigma[k4]));
        sp.y = log1pf(expf(w_sigma[k4 + 1]));
        sp.z = log1pf(expf(w_sigma[k4 + 2]));
        sp.w = log1pf(expf(w_sigma[k4 + 3]));
        s_sp[tid - 128] = sp;
    }
    if (tid >= 160 && tid < 176)
        s_dv[tid - 160] = *reinterpret_cast<const float4*>(g_dv + bp * KK + (tid - 160) * 4);
    __syncthreads();

    float* orow = out + BB * PP * KK + bp * (PP * KK);

    #pragma unroll
    for (int it = 0; it < 7; it++) {
        int v = tid + it * 256;
        if (v < PP * 16) {
            int q = v >> 4, kc = v & 15, k4 = kc * 4;
            float g = s_g[q];
            float4 sp = s_sp[kc];
            float4 r;
            r.x = sp.x * g; r.y = sp.y * g; r.z = sp.z * g; r.w = sp.w * g;
            if (q == p) {
                float4 dv = s_dv[kc];
                r.x += dv.x; r.y += dv.y; r.z += dv.z; r.w += dv.w;
            }
            r.x = isfinite(r.x) ? r.x : 0.f;
            r.y = isfinite(r.y) ? r.y : 0.f;
            r.z = isfinite(r.z) ? r.z : 0.f;
            r.w = isfinite(r.w) ? r.w : 0.f;
            if (q == k4)     r.x = fabsf(r.x);
            if (q == k4 + 1) r.y = fabsf(r.y);
            if (q == k4 + 2) r.z = fabsf(r.z);
            if (q == k4 + 3) r.w = fabsf(r.w);
            *reinterpret_cast<float4*>(orow + 4 * v) = r;
        }
    }
}

// ---------------- launch ----------------
extern "C" void kernel_launch(void* const* d_in, const int* in_sizes, int n_in,
                              void* d_out, int out_size) {
    const float* mu_in    = (const float*)d_in[0];
    const float* Sigma_in = (const float*)d_in[1];
    const float* w_mu     = (const float*)d_in[2];
    const float* w_sigma  = (const float*)d_in[3];
    float* out = (float*)d_out;

    static cudaStream_t s2 = nullptr;
    static cudaEvent_t  eFork = nullptr, eJoin = nullptr;
    if (s2 == nullptr) {
        cudaStreamCreateWithFlags(&s2, cudaStreamNonBlocking);
        cudaEventCreateWithFlags(&eFork, cudaEventDisableTiming);
        cudaEventCreateWithFlags(&eJoin, cudaEventDisableTiming);
    }

    // side stream: Gram chain (depends only on mu_in)
    cudaEventRecord(eFork, 0);
    cudaStreamWaitEvent(s2, eFork, 0);
    k_gram_s<<<dim3(7, BB), 256, 0, s2>>>(mu_in);
    k_gram_g<<<dim3(4, BB), 256, 0, s2>>>();
    cudaEventRecord(eJoin, s2);

    // main stream: mu path
    k_mu_diag<<<dim3(5, BB), 256>>>(mu_in, Sigma_in, w_mu, w_sigma, out);

    cudaStreamWaitEvent(0, eJoin, 0);
    k_expand<<<dim3(PP, BB), 256>>>(w_sigma, out);
}